// round 1
// baseline (speedup 1.0000x reference)
#include <cuda_runtime.h>
#include <math_constants.h>

#define BATCH 4
#define SEQ   4096
#define DIM   256

// Scratch: Q,K stored transposed [b][d][n]; V natural [b][n][d]
static __device__ float g_Q[(size_t)BATCH * SEQ * DIM];
static __device__ float g_K[(size_t)BATCH * SEQ * DIM];
static __device__ float g_V[(size_t)BATCH * SEQ * DIM];

// ---------------------------------------------------------------------------
// Projection: out = x @ W + b.  x:[16384,256], W:[256,256], b:[256].
// which: 0 -> g_Q (transposed), 1 -> g_K (transposed), 2 -> g_V (natural)
// Block: 256 threads, 64x64 output tile, K-chunks of 32.
// ---------------------------------------------------------------------------
__global__ __launch_bounds__(256) void proj_kernel(
    const float* __restrict__ x, const float* __restrict__ W,
    const float* __restrict__ bias, int which)
{
    __shared__ float Xt[32][68];   // [k][m], padded
    __shared__ float Ws[32][64];   // [k][n]

    float* out = (which == 0) ? g_Q : (which == 1) ? g_K : g_V;

    const int m0 = blockIdx.x * 64;
    const int n0 = blockIdx.y * 64;
    const int tid = threadIdx.x;
    const int ty = tid >> 4;       // 0..15
    const int tx = tid & 15;       // 0..15

    float acc[4][4];
#pragma unroll
    for (int i = 0; i < 4; i++)
#pragma unroll
        for (int j = 0; j < 4; j++) acc[i][j] = 0.f;

    for (int k0 = 0; k0 < DIM; k0 += 32) {
        __syncthreads();
        // X chunk transposed: Xt[k][m] = x[m0+m][k0+k]
        {
            const int k = tid & 31;
            const int mb = tid >> 5;   // 0..7
#pragma unroll
            for (int it = 0; it < 8; it++) {
                int m = it * 8 + mb;
                Xt[k][m] = x[(size_t)(m0 + m) * DIM + k0 + k];
            }
        }
        // W chunk natural: Ws[k][n] = W[k0+k][n0+n]
        {
            const int kb = tid >> 4;            // 0..15
            const int n4 = (tid & 15) << 2;
#pragma unroll
            for (int it = 0; it < 2; it++) {
                int k = it * 16 + kb;
                *(float4*)&Ws[k][n4] =
                    *(const float4*)&W[(size_t)(k0 + k) * DIM + n0 + n4];
            }
        }
        __syncthreads();
#pragma unroll
        for (int k = 0; k < 32; k++) {
            float4 a4 = *(float4*)&Xt[k][ty << 2];
            float4 b4 = *(float4*)&Ws[k][tx << 2];
            float av[4] = {a4.x, a4.y, a4.z, a4.w};
            float bv[4] = {b4.x, b4.y, b4.z, b4.w};
#pragma unroll
            for (int i = 0; i < 4; i++)
#pragma unroll
                for (int j = 0; j < 4; j++)
                    acc[i][j] = fmaf(av[i], bv[j], acc[i][j]);
        }
    }

    float4 bv4 = *(const float4*)&bias[n0 + (tx << 2)];
    float bb[4] = {bv4.x, bv4.y, bv4.z, bv4.w};

    if (which != 2) {
        // transposed store: out[b][e][nseq]
        const int b = m0 >> 12;           // m0 / 4096
        const int s0 = m0 & 4095;
#pragma unroll
        for (int j = 0; j < 4; j++) {
            float4 t = make_float4(acc[0][j] + bb[j], acc[1][j] + bb[j],
                                   acc[2][j] + bb[j], acc[3][j] + bb[j]);
            *(float4*)&out[(size_t)b * SEQ * DIM +
                           (size_t)(n0 + (tx << 2) + j) * SEQ + s0 + (ty << 2)] = t;
        }
    } else {
        // natural store: out[m][e]
#pragma unroll
        for (int i = 0; i < 4; i++) {
            float4 t = make_float4(acc[i][0] + bb[0], acc[i][1] + bb[1],
                                   acc[i][2] + bb[2], acc[i][3] + bb[3]);
            *(float4*)&out[(size_t)(m0 + (ty << 2) + i) * DIM + n0 + (tx << 2)] = t;
        }
    }
}

// ---------------------------------------------------------------------------
// Flash attention, fp32 FFMA. One block = (batch b, 64-query tile).
// 256 threads as 16x16; each thread: 4x4 score tile, 4x(4x4) output tile.
// ---------------------------------------------------------------------------
#define SMEM_FLOATS (256 * 68 + 32 * 68 + 64 * 68 + 16 * 260)
#define SMEM_BYTES (SMEM_FLOATS * 4)

__global__ __launch_bounds__(256) void attn_kernel(float* __restrict__ out)
{
    extern __shared__ float sm[];
    float(*Qt)[68]  = (float(*)[68])(sm);                               // [d=256][q=64]
    float(*Kt)[68]  = (float(*)[68])(sm + 256 * 68);                    // [k=32][key=64]
    float(*Pt)[68]  = (float(*)[68])(sm + 256 * 68 + 32 * 68);          // [key=64][q=64]
    float(*Vs)[260] = (float(*)[260])(sm + 256 * 68 + 32 * 68 + 64 * 68); // [kk=16][c=256]

    const int b = blockIdx.y;
    const int q0 = blockIdx.x * 64;
    const int tid = threadIdx.x;
    const int ty = tid >> 4;
    const int tx = tid & 15;
    const size_t bbase = (size_t)b * SEQ * DIM;

    // Load resident Q tile: Qt[d][q] (g_Q already [b][d][n])
    {
        const int dq = tid >> 4;
        const int q4 = (tid & 15) << 2;
#pragma unroll
        for (int it = 0; it < 16; it++) {
            int d = it * 16 + dq;
            *(float4*)&Qt[d][q4] =
                *(const float4*)&g_Q[bbase + (size_t)d * SEQ + q0 + q4];
        }
    }

    float o[4][4][4];  // [i(row)][c(col-chunk)][j]
#pragma unroll
    for (int i = 0; i < 4; i++)
#pragma unroll
        for (int c = 0; c < 4; c++)
#pragma unroll
            for (int j = 0; j < 4; j++) o[i][c][j] = 0.f;

    float mrow[4], lrow[4];
#pragma unroll
    for (int i = 0; i < 4; i++) { mrow[i] = -CUDART_INF_F; lrow[i] = 0.f; }

    const float SC = 0.0625f * 1.4426950408889634f;  // 1/sqrt(D) * log2(e)

#pragma unroll 1
    for (int kt = 0; kt < 64; kt++) {
        const int key0 = kt * 64;

        // ---- scores: acc = Q . K^T over D in chunks of 32 ----
        float acc[4][4];
#pragma unroll
        for (int i = 0; i < 4; i++)
#pragma unroll
            for (int j = 0; j < 4; j++) acc[i][j] = 0.f;

#pragma unroll 1
        for (int dc = 0; dc < 8; dc++) {
            __syncthreads();
            {
                const int kq = tid >> 4;
                const int key4 = (tid & 15) << 2;
#pragma unroll
                for (int it = 0; it < 2; it++) {
                    int k = it * 16 + kq;
                    *(float4*)&Kt[k][key4] =
                        *(const float4*)&g_K[bbase + (size_t)(dc * 32 + k) * SEQ + key0 + key4];
                }
            }
            __syncthreads();
#pragma unroll
            for (int k = 0; k < 32; k++) {
                float4 a4 = *(float4*)&Qt[dc * 32 + k][ty << 2];
                float4 k4 = *(float4*)&Kt[k][tx << 2];
                float av[4] = {a4.x, a4.y, a4.z, a4.w};
                float kv[4] = {k4.x, k4.y, k4.z, k4.w};
#pragma unroll
                for (int i = 0; i < 4; i++)
#pragma unroll
                    for (int j = 0; j < 4; j++)
                        acc[i][j] = fmaf(av[i], kv[j], acc[i][j]);
            }
        }

        // ---- online softmax (log2 domain) ----
        float p[4][4];
#pragma unroll
        for (int i = 0; i < 4; i++) {
            float s[4];
#pragma unroll
            for (int j = 0; j < 4; j++) s[j] = acc[i][j] * SC;
            float rmax = fmaxf(fmaxf(s[0], s[1]), fmaxf(s[2], s[3]));
#pragma unroll
            for (int off = 1; off < 16; off <<= 1)
                rmax = fmaxf(rmax, __shfl_xor_sync(0xffffffffu, rmax, off));
            float mnew = fmaxf(mrow[i], rmax);
            float corr = exp2f(mrow[i] - mnew);
            mrow[i] = mnew;
            float rs = 0.f;
#pragma unroll
            for (int j = 0; j < 4; j++) {
                p[i][j] = exp2f(s[j] - mnew);
                rs += p[i][j];
            }
#pragma unroll
            for (int off = 1; off < 16; off <<= 1)
                rs += __shfl_xor_sync(0xffffffffu, rs, off);
            lrow[i] = lrow[i] * corr + rs;
#pragma unroll
            for (int c = 0; c < 4; c++)
#pragma unroll
                for (int j = 0; j < 4; j++) o[i][c][j] *= corr;
        }

        // ---- P to smem transposed: Pt[key][q] ----
#pragma unroll
        for (int j = 0; j < 4; j++)
#pragma unroll
            for (int i = 0; i < 4; i++)
                Pt[(tx << 2) + j][(ty << 2) + i] = p[i][j];
        __syncthreads();

        // ---- O += P @ V, V streamed in 16-key chunks ----
#pragma unroll 1
        for (int vc = 0; vc < 4; vc++) {
            {
                const int c4 = (tid & 63) << 2;
                const int kkb = tid >> 6;   // 0..3
#pragma unroll
                for (int it = 0; it < 4; it++) {
                    int kk = it * 4 + kkb;
                    *(float4*)&Vs[kk][c4] =
                        *(const float4*)&g_V[bbase + (size_t)(key0 + vc * 16 + kk) * DIM + c4];
                }
            }
            __syncthreads();
#pragma unroll
            for (int kk = 0; kk < 16; kk++) {
                float4 p4 = *(float4*)&Pt[vc * 16 + kk][ty << 2];
                float pv[4] = {p4.x, p4.y, p4.z, p4.w};
#pragma unroll
                for (int c = 0; c < 4; c++) {
                    float4 v4 = *(float4*)&Vs[kk][c * 64 + (tx << 2)];
                    float vv[4] = {v4.x, v4.y, v4.z, v4.w};
#pragma unroll
                    for (int i = 0; i < 4; i++)
#pragma unroll
                        for (int j = 0; j < 4; j++)
                            o[i][c][j] = fmaf(pv[i], vv[j], o[i][c][j]);
                }
            }
            __syncthreads();
        }
    }

    // ---- epilogue: normalize and write ----
#pragma unroll
    for (int i = 0; i < 4; i++) {
        float inv = 1.0f / lrow[i];
        size_t row = ((size_t)b * SEQ + q0 + (ty << 2) + i) * DIM;
#pragma unroll
        for (int c = 0; c < 4; c++) {
            float4 t = make_float4(o[i][c][0] * inv, o[i][c][1] * inv,
                                   o[i][c][2] * inv, o[i][c][3] * inv);
            *(float4*)&out[row + c * 64 + (tx << 2)] = t;
        }
    }
}

// ---------------------------------------------------------------------------
extern "C" void kernel_launch(void* const* d_in, const int* in_sizes, int n_in,
                              void* d_out, int out_size)
{
    const float* x  = (const float*)d_in[0];
    const float* Wk = (const float*)d_in[1];
    const float* bk = (const float*)d_in[2];
    const float* Wq = (const float*)d_in[3];
    const float* bq = (const float*)d_in[4];
    const float* Wv = (const float*)d_in[5];
    const float* bv = (const float*)d_in[6];
    float* out = (float*)d_out;

    dim3 pgrid(BATCH * SEQ / 64, DIM / 64);   // (256, 4)
    proj_kernel<<<pgrid, 256>>>(x, Wq, bq, 0);
    proj_kernel<<<pgrid, 256>>>(x, Wk, bk, 1);
    proj_kernel<<<pgrid, 256>>>(x, Wv, bv, 2);

    cudaFuncSetAttribute(attn_kernel, cudaFuncAttributeMaxDynamicSharedMemorySize,
                         SMEM_BYTES);
    attn_kernel<<<dim3(SEQ / 64, BATCH), 256, SMEM_BYTES>>>(out);
}

// round 3
// speedup vs baseline: 2.4080x; 2.4080x over previous
#include <cuda_runtime.h>
#include <cuda_bf16.h>
#include <cstdint>

#define BATCH 4
#define SEQ   4096
#define DIM   256

// Row stride of bf16 smem tiles (padded: 256 + 8 elems = 528 bytes)
#define RSB   528

// Split-bf16 scratch, all row-major [b*SEQ][DIM]
static __device__ __align__(16) __nv_bfloat16 g_Qh[(size_t)BATCH * SEQ * DIM];
static __device__ __align__(16) __nv_bfloat16 g_Ql[(size_t)BATCH * SEQ * DIM];
static __device__ __align__(16) __nv_bfloat16 g_Kh[(size_t)BATCH * SEQ * DIM];
static __device__ __align__(16) __nv_bfloat16 g_Kl[(size_t)BATCH * SEQ * DIM];
static __device__ __align__(16) __nv_bfloat16 g_Vh[(size_t)BATCH * SEQ * DIM];
static __device__ __align__(16) __nv_bfloat16 g_Vl[(size_t)BATCH * SEQ * DIM];

// ---------------------------------------------------------------------------
// Helpers (all compute_103-legal: mma.sync / ldmatrix / cp.async)
// ---------------------------------------------------------------------------
__device__ __forceinline__ uint32_t smem_to_u32(const void* p) {
    uint32_t a;
    asm("{ .reg .u64 t; cvta.to.shared.u64 t, %1; cvt.u32.u64 %0, t; }"
        : "=r"(a) : "l"(p));
    return a;
}

__device__ __forceinline__ void mma_bf16(float* d, const uint32_t* a, const uint32_t* b) {
    asm volatile(
        "mma.sync.aligned.m16n8k16.row.col.f32.bf16.bf16.f32 "
        "{%0,%1,%2,%3}, {%4,%5,%6,%7}, {%8,%9}, {%0,%1,%2,%3};"
        : "+f"(d[0]), "+f"(d[1]), "+f"(d[2]), "+f"(d[3])
        : "r"(a[0]), "r"(a[1]), "r"(a[2]), "r"(a[3]), "r"(b[0]), "r"(b[1]));
}

__device__ __forceinline__ void ldsm_x4(uint32_t* r, uint32_t addr) {
    asm volatile("ldmatrix.sync.aligned.m8n8.x4.shared.b16 {%0,%1,%2,%3}, [%4];"
        : "=r"(r[0]), "=r"(r[1]), "=r"(r[2]), "=r"(r[3]) : "r"(addr));
}
__device__ __forceinline__ void ldsm_x4_t(uint32_t* r, uint32_t addr) {
    asm volatile("ldmatrix.sync.aligned.m8n8.x4.trans.shared.b16 {%0,%1,%2,%3}, [%4];"
        : "=r"(r[0]), "=r"(r[1]), "=r"(r[2]), "=r"(r[3]) : "r"(addr));
}

__device__ __forceinline__ void cp16(uint32_t dst, const void* src) {
    asm volatile("cp.async.cg.shared.global [%0], [%1], 16;"
                 :: "r"(dst), "l"(src));
}
#define CP_COMMIT() asm volatile("cp.async.commit_group;" ::: "memory")
#define CP_WAIT(n)  asm volatile("cp.async.wait_group %0;" :: "n"(n) : "memory")

__device__ __forceinline__ uint32_t pack_bf(__nv_bfloat16 a, __nv_bfloat16 b) {
    return (uint32_t)__bfloat16_as_ushort(a) | ((uint32_t)__bfloat16_as_ushort(b) << 16);
}
__device__ __forceinline__ void split2(float x, __nv_bfloat16& h, __nv_bfloat16& l) {
    h = __float2bfloat16(x);
    l = __float2bfloat16(x - __bfloat162float(h));
}

// ---------------------------------------------------------------------------
// Projection (FFMA, known-good core from R1): out = x@W + b, split-bf16 stores.
// which: 0 -> Q, 1 -> K, 2 -> V   (all row-major [m][e])
// ---------------------------------------------------------------------------
__global__ __launch_bounds__(256) void proj_kernel(
    const float* __restrict__ x, const float* __restrict__ W,
    const float* __restrict__ bias, int which)
{
    __shared__ float Xt[32][68];
    __shared__ float Ws[32][64];

    __nv_bfloat16* oh = (which == 0) ? g_Qh : (which == 1) ? g_Kh : g_Vh;
    __nv_bfloat16* ol = (which == 0) ? g_Ql : (which == 1) ? g_Kl : g_Vl;

    const int m0 = blockIdx.x * 64;
    const int n0 = blockIdx.y * 64;
    const int tid = threadIdx.x;
    const int ty = tid >> 4;
    const int tx = tid & 15;

    float acc[4][4];
#pragma unroll
    for (int i = 0; i < 4; i++)
#pragma unroll
        for (int j = 0; j < 4; j++) acc[i][j] = 0.f;

    for (int k0 = 0; k0 < DIM; k0 += 32) {
        __syncthreads();
        {
            const int k = tid & 31;
            const int mb = tid >> 5;
#pragma unroll
            for (int it = 0; it < 8; it++) {
                int m = it * 8 + mb;
                Xt[k][m] = x[(size_t)(m0 + m) * DIM + k0 + k];
            }
        }
        {
            const int kb = tid >> 4;
            const int n4 = (tid & 15) << 2;
#pragma unroll
            for (int it = 0; it < 2; it++) {
                int k = it * 16 + kb;
                *(float4*)&Ws[k][n4] = *(const float4*)&W[(size_t)(k0 + k) * DIM + n0 + n4];
            }
        }
        __syncthreads();
#pragma unroll
        for (int k = 0; k < 32; k++) {
            float4 a4 = *(float4*)&Xt[k][ty << 2];
            float4 b4 = *(float4*)&Ws[k][tx << 2];
            float av[4] = {a4.x, a4.y, a4.z, a4.w};
            float bv[4] = {b4.x, b4.y, b4.z, b4.w};
#pragma unroll
            for (int i = 0; i < 4; i++)
#pragma unroll
                for (int j = 0; j < 4; j++)
                    acc[i][j] = fmaf(av[i], bv[j], acc[i][j]);
        }
    }

    float4 bv4 = *(const float4*)&bias[n0 + (tx << 2)];
    float bb[4] = {bv4.x, bv4.y, bv4.z, bv4.w};

#pragma unroll
    for (int i = 0; i < 4; i++) {
        __nv_bfloat16 h[4], l[4];
#pragma unroll
        for (int j = 0; j < 4; j++) split2(acc[i][j] + bb[j], h[j], l[j]);
        size_t base = (size_t)(m0 + (ty << 2) + i) * DIM + n0 + (tx << 2);
        *(uint2*)&oh[base] = make_uint2(pack_bf(h[0], h[1]), pack_bf(h[2], h[3]));
        *(uint2*)&ol[base] = make_uint2(pack_bf(l[0], l[1]), pack_bf(l[2], l[3]));
    }
}

// ---------------------------------------------------------------------------
// Attention via mma.sync bf16 (3-pass split). CTA = 128 queries x batch.
// 8 warps, each owns a 16-query strip. 32-key tiles, K & V both resident.
// SMEM: Qh|Ql (128 rows) + Kh|Kl|Vh|Vl (32 rows each), padded rows of 528B.
// ---------------------------------------------------------------------------
#define QH_OFF 0
#define QL_OFF (128 * RSB)            // 67584
#define KH_OFF (QL_OFF + 128 * RSB)   // 135168
#define KL_OFF (KH_OFF + 32 * RSB)
#define VH_OFF (KL_OFF + 32 * RSB)
#define VL_OFF (VH_OFF + 32 * RSB)
#define ATTN_SMEM (VL_OFF + 32 * RSB) // 202752

__global__ __launch_bounds__(256, 1) void attn_mma(float* __restrict__ out)
{
    extern __shared__ char smem[];
    const uint32_t sb = smem_to_u32(smem);
    const int tid = threadIdx.x;
    const int lane = tid & 31;
    const int w = tid >> 5;
    const int b = blockIdx.y;
    const int q0 = blockIdx.x * 128;

    const uint32_t sQH = sb + QH_OFF, sQL = sb + QL_OFF;
    const uint32_t sKH = sb + KH_OFF, sKL = sb + KL_OFF;
    const uint32_t sVH = sb + VH_OFF, sVL = sb + VL_OFF;

    // ---- preamble: async-load Q (resident), K(0), V(0) ----
    {
        const size_t qg = (size_t)(b * SEQ + q0) * DIM;
#pragma unroll
        for (int i = 0; i < 16; i++) {
            int idx = tid + i * 256;
            int row = idx >> 5, ch = idx & 31;
            uint32_t d = (uint32_t)row * RSB + ch * 16;
            size_t g = qg + (size_t)row * DIM + ch * 8;
            cp16(sQH + d, g_Qh + g);
            cp16(sQL + d, g_Ql + g);
        }
        const size_t kg = (size_t)b * SEQ * DIM;
#pragma unroll
        for (int i = 0; i < 4; i++) {
            int idx = tid + i * 256;
            int row = idx >> 5, ch = idx & 31;
            uint32_t d = (uint32_t)row * RSB + ch * 16;
            size_t g = kg + (size_t)row * DIM + ch * 8;
            cp16(sKH + d, g_Kh + g);
            cp16(sKL + d, g_Kl + g);
            cp16(sVH + d, g_Vh + g);
            cp16(sVL + d, g_Vl + g);
        }
    }
    CP_COMMIT();
    CP_WAIT(0);
    __syncthreads();

    // per-thread ldmatrix address offsets
    const uint32_t qoff = (uint32_t)(16 * w + (lane & 15)) * RSB + ((lane & 16) ? 16u : 0u);
    const uint32_t koff = (uint32_t)((lane & 7) + ((lane & 16) ? 8 : 0)) * RSB + ((lane & 8) ? 16u : 0u);
    const uint32_t voff = (uint32_t)((lane & 7) + ((lane & 8) ? 8 : 0)) * RSB + ((lane & 16) ? 16u : 0u);

    float oacc[32][4];
#pragma unroll
    for (int i = 0; i < 32; i++)
#pragma unroll
        for (int j = 0; j < 4; j++) oacc[i][j] = 0.f;
    float lsum0 = 0.f, lsum1 = 0.f;

    const float SC = 0.0625f * 1.4426950408889634f;  // 1/sqrt(256) * log2(e)

#pragma unroll 1
    for (int kt = 0; kt < 128; kt++) {
        // ======== S = Q . K^T  (3-pass split, 16x32 per warp) ========
        float sacc[4][4];
#pragma unroll
        for (int i = 0; i < 4; i++)
#pragma unroll
            for (int j = 0; j < 4; j++) sacc[i][j] = 0.f;

#pragma unroll 4
        for (int ks = 0; ks < 16; ks++) {
            uint32_t qh[4], ql[4], kf[2][4], lf[2][4];
            ldsm_x4(qh, sQH + qoff + ks * 32);
            ldsm_x4(ql, sQL + qoff + ks * 32);
#pragma unroll
            for (int np = 0; np < 2; np++) {
                ldsm_x4(kf[np], sKH + koff + (uint32_t)np * 16 * RSB + ks * 32);
                ldsm_x4(lf[np], sKL + koff + (uint32_t)np * 16 * RSB + ks * 32);
            }
#pragma unroll
            for (int np = 0; np < 2; np++)
#pragma unroll
                for (int h = 0; h < 2; h++) {
                    const int nt = np * 2 + h;
                    mma_bf16(sacc[nt], qh, &kf[np][2 * h]);
                    mma_bf16(sacc[nt], qh, &lf[np][2 * h]);
                    mma_bf16(sacc[nt], ql, &kf[np][2 * h]);
                }
        }
        __syncthreads();  // all warps done reading K buffer

        // ---- prefetch K(kt+1) (lands under softmax + PV) ----
        if (kt < 127) {
            const size_t kg = ((size_t)b * SEQ + (size_t)(kt + 1) * 32) * DIM;
#pragma unroll
            for (int i = 0; i < 4; i++) {
                int idx = tid + i * 256;
                int row = idx >> 5, ch = idx & 31;
                uint32_t d = (uint32_t)row * RSB + ch * 16;
                size_t g = kg + (size_t)row * DIM + ch * 8;
                cp16(sKH + d, g_Kh + g);
                cp16(sKL + d, g_Kl + g);
            }
            CP_COMMIT();
        }

        // ======== softmax (no max-sub; normalize in epilogue) ========
        uint32_t Ph[2][4], Pl[2][4];
#pragma unroll
        for (int nt = 0; nt < 4; nt++) {
            float p0 = exp2f(sacc[nt][0] * SC);
            float p1 = exp2f(sacc[nt][1] * SC);
            float p2 = exp2f(sacc[nt][2] * SC);
            float p3 = exp2f(sacc[nt][3] * SC);
            lsum0 += p0 + p1;
            lsum1 += p2 + p3;
            __nv_bfloat16 h0, l0, h1, l1, h2, l2, h3, l3;
            split2(p0, h0, l0); split2(p1, h1, l1);
            split2(p2, h2, l2); split2(p3, h3, l3);
            const int j = nt >> 1, bs = (nt & 1) * 2;
            Ph[j][bs]     = pack_bf(h0, h1);
            Ph[j][bs + 1] = pack_bf(h2, h3);
            Pl[j][bs]     = pack_bf(l0, l1);
            Pl[j][bs + 1] = pack_bf(l2, l3);
        }

        if (kt < 127) { CP_WAIT(1); } else { CP_WAIT(0); }  // V(kt) complete
        __syncthreads();

        // ======== O += P . V  (16x256 per warp, 3-pass split) ========
#pragma unroll
        for (int dblk = 0; dblk < 4; dblk++)
#pragma unroll
            for (int kc = 0; kc < 2; kc++) {
                uint32_t vhf[4][4], vlf[4][4];
#pragma unroll
                for (int q = 0; q < 4; q++) {
                    uint32_t a = (uint32_t)kc * 16 * RSB + voff + (uint32_t)(dblk * 64 + q * 16) * 2;
                    ldsm_x4_t(vhf[q], sVH + a);
                    ldsm_x4_t(vlf[q], sVL + a);
                }
#pragma unroll
                for (int q = 0; q < 4; q++)
#pragma unroll
                    for (int h = 0; h < 2; h++) {
                        const int nto = dblk * 8 + q * 2 + h;
                        mma_bf16(oacc[nto], Ph[kc], &vhf[q][2 * h]);
                        mma_bf16(oacc[nto], Ph[kc], &vlf[q][2 * h]);
                        mma_bf16(oacc[nto], Pl[kc], &vhf[q][2 * h]);
                    }
            }
        __syncthreads();  // all warps done reading V buffer

        // ---- prefetch V(kt+1); ensure K(kt+1) complete before next S ----
        if (kt < 127) {
            const size_t vg = ((size_t)b * SEQ + (size_t)(kt + 1) * 32) * DIM;
#pragma unroll
            for (int i = 0; i < 4; i++) {
                int idx = tid + i * 256;
                int row = idx >> 5, ch = idx & 31;
                uint32_t d = (uint32_t)row * RSB + ch * 16;
                size_t g = vg + (size_t)row * DIM + ch * 8;
                cp16(sVH + d, g_Vh + g);
                cp16(sVL + d, g_Vl + g);
            }
            CP_COMMIT();
            CP_WAIT(1);   // K(kt+1) landed; V(kt+1) may still be in flight
        }
        __syncthreads();
    }

    // ======== epilogue: normalize rows and store ========
    lsum0 += __shfl_xor_sync(0xffffffffu, lsum0, 1);
    lsum0 += __shfl_xor_sync(0xffffffffu, lsum0, 2);
    lsum1 += __shfl_xor_sync(0xffffffffu, lsum1, 1);
    lsum1 += __shfl_xor_sync(0xffffffffu, lsum1, 2);
    const float inv0 = 1.0f / lsum0;
    const float inv1 = 1.0f / lsum1;

    const int r0 = q0 + 16 * w + (lane >> 2);
    const size_t base0 = ((size_t)b * SEQ + r0) * DIM + (lane & 3) * 2;
    const size_t base1 = base0 + (size_t)8 * DIM;
#pragma unroll
    for (int nto = 0; nto < 32; nto++) {
        float2 v0 = make_float2(oacc[nto][0] * inv0, oacc[nto][1] * inv0);
        float2 v1 = make_float2(oacc[nto][2] * inv1, oacc[nto][3] * inv1);
        *(float2*)&out[base0 + nto * 8] = v0;
        *(float2*)&out[base1 + nto * 8] = v1;
    }
}

// ---------------------------------------------------------------------------
extern "C" void kernel_launch(void* const* d_in, const int* in_sizes, int n_in,
                              void* d_out, int out_size)
{
    const float* x  = (const float*)d_in[0];
    const float* Wk = (const float*)d_in[1];
    const float* bk = (const float*)d_in[2];
    const float* Wq = (const float*)d_in[3];
    const float* bq = (const float*)d_in[4];
    const float* Wv = (const float*)d_in[5];
    const float* bv = (const float*)d_in[6];
    float* out = (float*)d_out;

    dim3 pgrid(BATCH * SEQ / 64, DIM / 64);   // (256, 4)
    proj_kernel<<<pgrid, 256>>>(x, Wq, bq, 0);
    proj_kernel<<<pgrid, 256>>>(x, Wk, bk, 1);
    proj_kernel<<<pgrid, 256>>>(x, Wv, bv, 2);

    cudaFuncSetAttribute(attn_mma, cudaFuncAttributeMaxDynamicSharedMemorySize,
                         ATTN_SMEM);
    attn_mma<<<dim3(SEQ / 128, BATCH), 256, ATTN_SMEM>>>(out);
}

// round 4
// speedup vs baseline: 2.7682x; 1.1496x over previous
#include <cuda_runtime.h>
#include <cuda_bf16.h>
#include <cstdint>

#define BATCH 4
#define SEQ   4096
#define DIM   256

// Row stride of bf16 smem tiles (padded: 256 + 8 elems = 528 bytes)
#define RSB   528

// Split-bf16 scratch, all row-major [b*SEQ][DIM]
static __device__ __align__(16) __nv_bfloat16 g_Qh[(size_t)BATCH * SEQ * DIM];
static __device__ __align__(16) __nv_bfloat16 g_Ql[(size_t)BATCH * SEQ * DIM];
static __device__ __align__(16) __nv_bfloat16 g_Kh[(size_t)BATCH * SEQ * DIM];
static __device__ __align__(16) __nv_bfloat16 g_Kl[(size_t)BATCH * SEQ * DIM];
static __device__ __align__(16) __nv_bfloat16 g_Vh[(size_t)BATCH * SEQ * DIM];
static __device__ __align__(16) __nv_bfloat16 g_Vl[(size_t)BATCH * SEQ * DIM];
// Split weights: [3][256*256] (0=Wq, 1=Wk, 2=Wv)
static __device__ __align__(16) __nv_bfloat16 g_Wh[3 * DIM * DIM];
static __device__ __align__(16) __nv_bfloat16 g_Wl[3 * DIM * DIM];

// ---------------------------------------------------------------------------
// Helpers (all compute_103-legal: mma.sync / ldmatrix / cp.async)
// ---------------------------------------------------------------------------
__device__ __forceinline__ uint32_t smem_to_u32(const void* p) {
    uint32_t a;
    asm("{ .reg .u64 t; cvta.to.shared.u64 t, %1; cvt.u32.u64 %0, t; }"
        : "=r"(a) : "l"(p));
    return a;
}

__device__ __forceinline__ void mma_bf16(float* d, const uint32_t* a, const uint32_t* b) {
    asm volatile(
        "mma.sync.aligned.m16n8k16.row.col.f32.bf16.bf16.f32 "
        "{%0,%1,%2,%3}, {%4,%5,%6,%7}, {%8,%9}, {%0,%1,%2,%3};"
        : "+f"(d[0]), "+f"(d[1]), "+f"(d[2]), "+f"(d[3])
        : "r"(a[0]), "r"(a[1]), "r"(a[2]), "r"(a[3]), "r"(b[0]), "r"(b[1]));
}

__device__ __forceinline__ void ldsm_x4(uint32_t* r, uint32_t addr) {
    asm volatile("ldmatrix.sync.aligned.m8n8.x4.shared.b16 {%0,%1,%2,%3}, [%4];"
        : "=r"(r[0]), "=r"(r[1]), "=r"(r[2]), "=r"(r[3]) : "r"(addr));
}
__device__ __forceinline__ void ldsm_x4_t(uint32_t* r, uint32_t addr) {
    asm volatile("ldmatrix.sync.aligned.m8n8.x4.trans.shared.b16 {%0,%1,%2,%3}, [%4];"
        : "=r"(r[0]), "=r"(r[1]), "=r"(r[2]), "=r"(r[3]) : "r"(addr));
}

__device__ __forceinline__ void cp16(uint32_t dst, const void* src) {
    asm volatile("cp.async.cg.shared.global [%0], [%1], 16;"
                 :: "r"(dst), "l"(src));
}
#define CP_COMMIT() asm volatile("cp.async.commit_group;" ::: "memory")
#define CP_WAIT(n)  asm volatile("cp.async.wait_group %0;" :: "n"(n) : "memory")

__device__ __forceinline__ uint32_t pack_bf(__nv_bfloat16 a, __nv_bfloat16 b) {
    return (uint32_t)__bfloat16_as_ushort(a) | ((uint32_t)__bfloat16_as_ushort(b) << 16);
}
__device__ __forceinline__ void split2(float x, __nv_bfloat16& h, __nv_bfloat16& l) {
    h = __float2bfloat16(x);
    l = __float2bfloat16(x - __bfloat162float(h));
}

// ---------------------------------------------------------------------------
// W pre-split: 3 x 256x256 fp32 -> split bf16
// ---------------------------------------------------------------------------
__global__ __launch_bounds__(256) void split_w_kernel(
    const float* __restrict__ Wq, const float* __restrict__ Wk,
    const float* __restrict__ Wv)
{
    const int wsel = blockIdx.y;
    const float* W = (wsel == 0) ? Wq : (wsel == 1) ? Wk : Wv;
    int idx = (blockIdx.x * 256 + threadIdx.x) * 4;   // grid.x = 64
    float4 v = *(const float4*)&W[idx];
    __nv_bfloat16 h[4], l[4];
    split2(v.x, h[0], l[0]); split2(v.y, h[1], l[1]);
    split2(v.z, h[2], l[2]); split2(v.w, h[3], l[3]);
    size_t base = (size_t)wsel * DIM * DIM + idx;
    *(uint2*)&g_Wh[base] = make_uint2(pack_bf(h[0], h[1]), pack_bf(h[2], h[3]));
    *(uint2*)&g_Wl[base] = make_uint2(pack_bf(l[0], l[1]), pack_bf(l[2], l[3]));
}

// ---------------------------------------------------------------------------
// Tensorized fused projections: Q/K/V = x @ W + b, split-bf16 in/out.
// CTA = 128 rows of x. x tile split in-kernel, resident in smem.
// W streamed in 32-k-row chunks, double-buffered cp.async.
// 8 warps x 16-row strips, each computes 16x256 fp32, 3-pass bf16 split.
// ---------------------------------------------------------------------------
#define PXH_OFF 0
#define PXL_OFF (128 * RSB)                 // 67584
#define PW_OFF  (PXL_OFF + 128 * RSB)       // 135168
#define PWBUF   (32 * RSB)                  // 16896 bytes per (h/l) buffer
#define PROJ_SMEM (PW_OFF + 4 * PWBUF)      // 202752

__global__ __launch_bounds__(256, 1) void proj_mma(
    const float* __restrict__ x,
    const float* __restrict__ bq, const float* __restrict__ bk,
    const float* __restrict__ bv)
{
    extern __shared__ char smem[];
    const uint32_t sb = smem_to_u32(smem);
    const int tid = threadIdx.x;
    const int lane = tid & 31;
    const int w = tid >> 5;
    const int m0 = blockIdx.x * 128;

    const uint32_t sXH = sb + PXH_OFF, sXL = sb + PXL_OFF;
    uint32_t sWH[2] = {sb + PW_OFF, sb + PW_OFF + 2 * PWBUF};
    uint32_t sWL[2] = {sb + PW_OFF + PWBUF, sb + PW_OFF + 3 * PWBUF};

    // ---- prefetch W chunk 0 (wsel=0, k0=0) ----
#pragma unroll
    for (int i = 0; i < 4; i++) {
        int idx = tid + i * 256;            // 1024 16B-lines per half
        int row = idx >> 5, c16 = idx & 31;
        uint32_t d = (uint32_t)row * RSB + c16 * 16;
        size_t g = (size_t)row * DIM + c16 * 8;
        cp16(sWH[0] + d, g_Wh + g);
        cp16(sWL[0] + d, g_Wl + g);
    }
    CP_COMMIT();

    // ---- load + split resident x tile ----
    {
#pragma unroll
        for (int i = 0; i < 32; i++) {
            int idx = tid + i * 256;        // 8192 float4
            int row = idx >> 6, c4 = idx & 63;
            float4 v = *(const float4*)&x[(size_t)(m0 + row) * DIM + c4 * 4];
            __nv_bfloat16 h[4], l[4];
            split2(v.x, h[0], l[0]); split2(v.y, h[1], l[1]);
            split2(v.z, h[2], l[2]); split2(v.w, h[3], l[3]);
            uint32_t d = (uint32_t)row * RSB + c4 * 8;
            *(uint2*)(smem + PXH_OFF + d) = make_uint2(pack_bf(h[0], h[1]), pack_bf(h[2], h[3]));
            *(uint2*)(smem + PXL_OFF + d) = make_uint2(pack_bf(l[0], l[1]), pack_bf(l[2], l[3]));
        }
    }

    // ldmatrix addressing
    const uint32_t aoff = (uint32_t)(16 * w + (lane & 15)) * RSB + ((lane & 16) ? 16u : 0u);
    const uint32_t boff = (uint32_t)((lane & 7) + ((lane & 8) ? 8 : 0)) * RSB + ((lane & 16) ? 16u : 0u);

    float oacc[32][4];
#pragma unroll
    for (int i = 0; i < 32; i++)
#pragma unroll
        for (int j = 0; j < 4; j++) oacc[i][j] = 0.f;

#pragma unroll 1
    for (int c = 0; c < 24; c++) {
        const int buf = c & 1;
        // prefetch chunk c+1
        if (c < 23) {
            const int wsel = (c + 1) >> 3;
            const int k0 = ((c + 1) & 7) * 32;
            const size_t gbase = (size_t)wsel * DIM * DIM + (size_t)k0 * DIM;
#pragma unroll
            for (int i = 0; i < 4; i++) {
                int idx = tid + i * 256;
                int row = idx >> 5, c16 = idx & 31;
                uint32_t d = (uint32_t)row * RSB + c16 * 16;
                size_t g = gbase + (size_t)row * DIM + c16 * 8;
                cp16(sWH[buf ^ 1] + d, g_Wh + g);
                cp16(sWL[buf ^ 1] + d, g_Wl + g);
            }
            CP_COMMIT();
            CP_WAIT(1);
        } else {
            CP_WAIT(0);
        }
        __syncthreads();

        // compute chunk c: 2 ksteps of 16
        const int kbase = (c & 7) * 32;
#pragma unroll
        for (int ks = 0; ks < 2; ks++) {
            uint32_t ah[4], al[4];
            ldsm_x4(ah, sXH + aoff + (uint32_t)(kbase + ks * 16) * 2);
            ldsm_x4(al, sXL + aoff + (uint32_t)(kbase + ks * 16) * 2);
#pragma unroll
            for (int nt = 0; nt < 16; nt++) {
                uint32_t bh[4], bl[4];
                uint32_t a = (uint32_t)ks * 16 * RSB + boff + (uint32_t)nt * 32;
                ldsm_x4_t(bh, sWH[buf] + a);
                ldsm_x4_t(bl, sWL[buf] + a);
#pragma unroll
                for (int h = 0; h < 2; h++) {
                    const int nto = nt * 2 + h;
                    mma_bf16(oacc[nto], ah, &bh[2 * h]);
                    mma_bf16(oacc[nto], ah, &bl[2 * h]);
                    mma_bf16(oacc[nto], al, &bh[2 * h]);
                }
            }
        }

        // ---- end of a weight: epilogue ----
        if ((c & 7) == 7) {
            const int wsel = c >> 3;
            const float* bias = (wsel == 0) ? bq : (wsel == 1) ? bk : bv;
            __nv_bfloat16* oh = (wsel == 0) ? g_Qh : (wsel == 1) ? g_Kh : g_Vh;
            __nv_bfloat16* ol = (wsel == 0) ? g_Ql : (wsel == 1) ? g_Kl : g_Vl;

            const int r0 = m0 + 16 * w + (lane >> 2);
            const size_t base0 = (size_t)r0 * DIM + (lane & 3) * 2;
            const size_t base1 = base0 + (size_t)8 * DIM;
#pragma unroll
            for (int nto = 0; nto < 32; nto++) {
                const int col = nto * 8 + (lane & 3) * 2;
                float b0 = bias[col], b1 = bias[col + 1];
                __nv_bfloat16 h0, l0, h1, l1;
                split2(oacc[nto][0] + b0, h0, l0);
                split2(oacc[nto][1] + b1, h1, l1);
                *(uint32_t*)&oh[base0 + nto * 8] = pack_bf(h0, h1);
                *(uint32_t*)&ol[base0 + nto * 8] = pack_bf(l0, l1);
                split2(oacc[nto][2] + b0, h0, l0);
                split2(oacc[nto][3] + b1, h1, l1);
                *(uint32_t*)&oh[base1 + nto * 8] = pack_bf(h0, h1);
                *(uint32_t*)&ol[base1 + nto * 8] = pack_bf(l0, l1);
                oacc[nto][0] = oacc[nto][1] = oacc[nto][2] = oacc[nto][3] = 0.f;
            }
        }
        __syncthreads();
    }
}

// ---------------------------------------------------------------------------
// Attention via mma.sync bf16 (3-pass split). CTA = 128 queries x batch.
// (unchanged from R3 — proven at 620us, rel_err 1.4e-5)
// ---------------------------------------------------------------------------
#define QH_OFF 0
#define QL_OFF (128 * RSB)
#define KH_OFF (QL_OFF + 128 * RSB)
#define KL_OFF (KH_OFF + 32 * RSB)
#define VH_OFF (KL_OFF + 32 * RSB)
#define VL_OFF (VH_OFF + 32 * RSB)
#define ATTN_SMEM (VL_OFF + 32 * RSB)

__global__ __launch_bounds__(256, 1) void attn_mma(float* __restrict__ out)
{
    extern __shared__ char smem[];
    const uint32_t sb = smem_to_u32(smem);
    const int tid = threadIdx.x;
    const int lane = tid & 31;
    const int w = tid >> 5;
    const int b = blockIdx.y;
    const int q0 = blockIdx.x * 128;

    const uint32_t sQH = sb + QH_OFF, sQL = sb + QL_OFF;
    const uint32_t sKH = sb + KH_OFF, sKL = sb + KL_OFF;
    const uint32_t sVH = sb + VH_OFF, sVL = sb + VL_OFF;

    {
        const size_t qg = (size_t)(b * SEQ + q0) * DIM;
#pragma unroll
        for (int i = 0; i < 16; i++) {
            int idx = tid + i * 256;
            int row = idx >> 5, ch = idx & 31;
            uint32_t d = (uint32_t)row * RSB + ch * 16;
            size_t g = qg + (size_t)row * DIM + ch * 8;
            cp16(sQH + d, g_Qh + g);
            cp16(sQL + d, g_Ql + g);
        }
        const size_t kg = (size_t)b * SEQ * DIM;
#pragma unroll
        for (int i = 0; i < 4; i++) {
            int idx = tid + i * 256;
            int row = idx >> 5, ch = idx & 31;
            uint32_t d = (uint32_t)row * RSB + ch * 16;
            size_t g = kg + (size_t)row * DIM + ch * 8;
            cp16(sKH + d, g_Kh + g);
            cp16(sKL + d, g_Kl + g);
            cp16(sVH + d, g_Vh + g);
            cp16(sVL + d, g_Vl + g);
        }
    }
    CP_COMMIT();
    CP_WAIT(0);
    __syncthreads();

    const uint32_t qoff = (uint32_t)(16 * w + (lane & 15)) * RSB + ((lane & 16) ? 16u : 0u);
    const uint32_t koff = (uint32_t)((lane & 7) + ((lane & 16) ? 8 : 0)) * RSB + ((lane & 8) ? 16u : 0u);
    const uint32_t voff = (uint32_t)((lane & 7) + ((lane & 8) ? 8 : 0)) * RSB + ((lane & 16) ? 16u : 0u);

    float oacc[32][4];
#pragma unroll
    for (int i = 0; i < 32; i++)
#pragma unroll
        for (int j = 0; j < 4; j++) oacc[i][j] = 0.f;
    float lsum0 = 0.f, lsum1 = 0.f;

    const float SC = 0.0625f * 1.4426950408889634f;

#pragma unroll 1
    for (int kt = 0; kt < 128; kt++) {
        float sacc[4][4];
#pragma unroll
        for (int i = 0; i < 4; i++)
#pragma unroll
            for (int j = 0; j < 4; j++) sacc[i][j] = 0.f;

#pragma unroll 4
        for (int ks = 0; ks < 16; ks++) {
            uint32_t qh[4], ql[4], kf[2][4], lf[2][4];
            ldsm_x4(qh, sQH + qoff + ks * 32);
            ldsm_x4(ql, sQL + qoff + ks * 32);
#pragma unroll
            for (int np = 0; np < 2; np++) {
                ldsm_x4(kf[np], sKH + koff + (uint32_t)np * 16 * RSB + ks * 32);
                ldsm_x4(lf[np], sKL + koff + (uint32_t)np * 16 * RSB + ks * 32);
            }
#pragma unroll
            for (int np = 0; np < 2; np++)
#pragma unroll
                for (int h = 0; h < 2; h++) {
                    const int nt = np * 2 + h;
                    mma_bf16(sacc[nt], qh, &kf[np][2 * h]);
                    mma_bf16(sacc[nt], qh, &lf[np][2 * h]);
                    mma_bf16(sacc[nt], ql, &kf[np][2 * h]);
                }
        }
        __syncthreads();

        if (kt < 127) {
            const size_t kg = ((size_t)b * SEQ + (size_t)(kt + 1) * 32) * DIM;
#pragma unroll
            for (int i = 0; i < 4; i++) {
                int idx = tid + i * 256;
                int row = idx >> 5, ch = idx & 31;
                uint32_t d = (uint32_t)row * RSB + ch * 16;
                size_t g = kg + (size_t)row * DIM + ch * 8;
                cp16(sKH + d, g_Kh + g);
                cp16(sKL + d, g_Kl + g);
            }
            CP_COMMIT();
        }

        uint32_t Ph[2][4], Pl[2][4];
#pragma unroll
        for (int nt = 0; nt < 4; nt++) {
            float p0 = exp2f(sacc[nt][0] * SC);
            float p1 = exp2f(sacc[nt][1] * SC);
            float p2 = exp2f(sacc[nt][2] * SC);
            float p3 = exp2f(sacc[nt][3] * SC);
            lsum0 += p0 + p1;
            lsum1 += p2 + p3;
            __nv_bfloat16 h0, l0, h1, l1, h2, l2, h3, l3;
            split2(p0, h0, l0); split2(p1, h1, l1);
            split2(p2, h2, l2); split2(p3, h3, l3);
            const int j = nt >> 1, bs = (nt & 1) * 2;
            Ph[j][bs]     = pack_bf(h0, h1);
            Ph[j][bs + 1] = pack_bf(h2, h3);
            Pl[j][bs]     = pack_bf(l0, l1);
            Pl[j][bs + 1] = pack_bf(l2, l3);
        }

        if (kt < 127) { CP_WAIT(1); } else { CP_WAIT(0); }
        __syncthreads();

#pragma unroll
        for (int dblk = 0; dblk < 4; dblk++)
#pragma unroll
            for (int kc = 0; kc < 2; kc++) {
                uint32_t vhf[4][4], vlf[4][4];
#pragma unroll
                for (int q = 0; q < 4; q++) {
                    uint32_t a = (uint32_t)kc * 16 * RSB + voff + (uint32_t)(dblk * 64 + q * 16) * 2;
                    ldsm_x4_t(vhf[q], sVH + a);
                    ldsm_x4_t(vlf[q], sVL + a);
                }
#pragma unroll
                for (int q = 0; q < 4; q++)
#pragma unroll
                    for (int h = 0; h < 2; h++) {
                        const int nto = dblk * 8 + q * 2 + h;
                        mma_bf16(oacc[nto], Ph[kc], &vhf[q][2 * h]);
                        mma_bf16(oacc[nto], Ph[kc], &vlf[q][2 * h]);
                        mma_bf16(oacc[nto], Pl[kc], &vhf[q][2 * h]);
                    }
            }
        __syncthreads();

        if (kt < 127) {
            const size_t vg = ((size_t)b * SEQ + (size_t)(kt + 1) * 32) * DIM;
#pragma unroll
            for (int i = 0; i < 4; i++) {
                int idx = tid + i * 256;
                int row = idx >> 5, ch = idx & 31;
                uint32_t d = (uint32_t)row * RSB + ch * 16;
                size_t g = vg + (size_t)row * DIM + ch * 8;
                cp16(sVH + d, g_Vh + g);
                cp16(sVL + d, g_Vl + g);
            }
            CP_COMMIT();
            CP_WAIT(1);
        }
        __syncthreads();
    }

    lsum0 += __shfl_xor_sync(0xffffffffu, lsum0, 1);
    lsum0 += __shfl_xor_sync(0xffffffffu, lsum0, 2);
    lsum1 += __shfl_xor_sync(0xffffffffu, lsum1, 1);
    lsum1 += __shfl_xor_sync(0xffffffffu, lsum1, 2);
    const float inv0 = 1.0f / lsum0;
    const float inv1 = 1.0f / lsum1;

    const int r0 = q0 + 16 * w + (lane >> 2);
    const size_t base0 = ((size_t)b * SEQ + r0) * DIM + (lane & 3) * 2;
    const size_t base1 = base0 + (size_t)8 * DIM;
#pragma unroll
    for (int nto = 0; nto < 32; nto++) {
        float2 v0 = make_float2(oacc[nto][0] * inv0, oacc[nto][1] * inv0);
        float2 v1 = make_float2(oacc[nto][2] * inv1, oacc[nto][3] * inv1);
        *(float2*)&out[base0 + nto * 8] = v0;
        *(float2*)&out[base1 + nto * 8] = v1;
    }
}

// ---------------------------------------------------------------------------
extern "C" void kernel_launch(void* const* d_in, const int* in_sizes, int n_in,
                              void* d_out, int out_size)
{
    const float* x  = (const float*)d_in[0];
    const float* Wk = (const float*)d_in[1];
    const float* bk = (const float*)d_in[2];
    const float* Wq = (const float*)d_in[3];
    const float* bq = (const float*)d_in[4];
    const float* Wv = (const float*)d_in[5];
    const float* bv = (const float*)d_in[6];
    float* out = (float*)d_out;

    split_w_kernel<<<dim3(64, 3), 256>>>(Wq, Wk, Wv);

    cudaFuncSetAttribute(proj_mma, cudaFuncAttributeMaxDynamicSharedMemorySize,
                         PROJ_SMEM);
    proj_mma<<<BATCH * SEQ / 128, 256, PROJ_SMEM>>>(x, bq, bk, bv);

    cudaFuncSetAttribute(attn_mma, cudaFuncAttributeMaxDynamicSharedMemorySize,
                         ATTN_SMEM);
    attn_mma<<<dim3(SEQ / 128, BATCH), 256, ATTN_SMEM>>>(out);
}

// round 5
// speedup vs baseline: 2.7697x; 1.0006x over previous
#include <cuda_runtime.h>
#include <cuda_bf16.h>
#include <cstdint>

#define BATCH 4
#define SEQ   4096
#define DIM   256

// Row stride of bf16 smem tiles (padded: 256 + 8 elems = 528 bytes)
#define RSB   528

// Split-bf16 scratch, all row-major [b*SEQ][DIM]
static __device__ __align__(16) __nv_bfloat16 g_Qh[(size_t)BATCH * SEQ * DIM];
static __device__ __align__(16) __nv_bfloat16 g_Ql[(size_t)BATCH * SEQ * DIM];
static __device__ __align__(16) __nv_bfloat16 g_Kh[(size_t)BATCH * SEQ * DIM];
static __device__ __align__(16) __nv_bfloat16 g_Kl[(size_t)BATCH * SEQ * DIM];
static __device__ __align__(16) __nv_bfloat16 g_Vh[(size_t)BATCH * SEQ * DIM];
static __device__ __align__(16) __nv_bfloat16 g_Vl[(size_t)BATCH * SEQ * DIM];
// Split weights: [3][256*256] (0=Wq, 1=Wk, 2=Wv)
static __device__ __align__(16) __nv_bfloat16 g_Wh[3 * DIM * DIM];
static __device__ __align__(16) __nv_bfloat16 g_Wl[3 * DIM * DIM];

// ---------------------------------------------------------------------------
// Helpers (all compute_103-legal: mma.sync / ldmatrix / cp.async)
// ---------------------------------------------------------------------------
__device__ __forceinline__ uint32_t smem_to_u32(const void* p) {
    uint32_t a;
    asm("{ .reg .u64 t; cvta.to.shared.u64 t, %1; cvt.u32.u64 %0, t; }"
        : "=r"(a) : "l"(p));
    return a;
}

__device__ __forceinline__ void mma_bf16(float* d, const uint32_t* a, const uint32_t* b) {
    asm volatile(
        "mma.sync.aligned.m16n8k16.row.col.f32.bf16.bf16.f32 "
        "{%0,%1,%2,%3}, {%4,%5,%6,%7}, {%8,%9}, {%0,%1,%2,%3};"
        : "+f"(d[0]), "+f"(d[1]), "+f"(d[2]), "+f"(d[3])
        : "r"(a[0]), "r"(a[1]), "r"(a[2]), "r"(a[3]), "r"(b[0]), "r"(b[1]));
}

__device__ __forceinline__ void ldsm_x4(uint32_t* r, uint32_t addr) {
    asm volatile("ldmatrix.sync.aligned.m8n8.x4.shared.b16 {%0,%1,%2,%3}, [%4];"
        : "=r"(r[0]), "=r"(r[1]), "=r"(r[2]), "=r"(r[3]) : "r"(addr));
}
__device__ __forceinline__ void ldsm_x4_t(uint32_t* r, uint32_t addr) {
    asm volatile("ldmatrix.sync.aligned.m8n8.x4.trans.shared.b16 {%0,%1,%2,%3}, [%4];"
        : "=r"(r[0]), "=r"(r[1]), "=r"(r[2]), "=r"(r[3]) : "r"(addr));
}

__device__ __forceinline__ void cp16(uint32_t dst, const void* src) {
    asm volatile("cp.async.cg.shared.global [%0], [%1], 16;"
                 :: "r"(dst), "l"(src));
}
#define CP_COMMIT() asm volatile("cp.async.commit_group;" ::: "memory")
#define CP_WAIT(n)  asm volatile("cp.async.wait_group %0;" :: "n"(n) : "memory")

__device__ __forceinline__ uint32_t pack_bf(__nv_bfloat16 a, __nv_bfloat16 b) {
    return (uint32_t)__bfloat16_as_ushort(a) | ((uint32_t)__bfloat16_as_ushort(b) << 16);
}
__device__ __forceinline__ void split2(float x, __nv_bfloat16& h, __nv_bfloat16& l) {
    h = __float2bfloat16(x);
    l = __float2bfloat16(x - __bfloat162float(h));
}

// ---------------------------------------------------------------------------
// W pre-split: 3 x 256x256 fp32 -> split bf16
// ---------------------------------------------------------------------------
__global__ __launch_bounds__(256) void split_w_kernel(
    const float* __restrict__ Wq, const float* __restrict__ Wk,
    const float* __restrict__ Wv)
{
    const int wsel = blockIdx.y;
    const float* W = (wsel == 0) ? Wq : (wsel == 1) ? Wk : Wv;
    int idx = (blockIdx.x * 256 + threadIdx.x) * 4;   // grid.x = 64
    float4 v = *(const float4*)&W[idx];
    __nv_bfloat16 h[4], l[4];
    split2(v.x, h[0], l[0]); split2(v.y, h[1], l[1]);
    split2(v.z, h[2], l[2]); split2(v.w, h[3], l[3]);
    size_t base = (size_t)wsel * DIM * DIM + idx;
    *(uint2*)&g_Wh[base] = make_uint2(pack_bf(h[0], h[1]), pack_bf(h[2], h[3]));
    *(uint2*)&g_Wl[base] = make_uint2(pack_bf(l[0], l[1]), pack_bf(l[2], l[3]));
}

// ---------------------------------------------------------------------------
// Tensorized fused projections: Q/K/V = x @ W + b, split-bf16 in/out.
// CTA = 128 rows of x. x tile split in-kernel, resident in smem.
// W streamed in 32-k-row chunks, double-buffered cp.async.
// 8 warps x 16-row strips, each computes 16x256 fp32, 3-pass bf16 split.
// ---------------------------------------------------------------------------
#define PXH_OFF 0
#define PXL_OFF (128 * RSB)                 // 67584
#define PW_OFF  (PXL_OFF + 128 * RSB)       // 135168
#define PWBUF   (32 * RSB)                  // 16896 bytes per (h/l) buffer
#define PROJ_SMEM (PW_OFF + 4 * PWBUF)      // 202752

__global__ __launch_bounds__(256, 1) void proj_mma(
    const float* __restrict__ x,
    const float* __restrict__ bq, const float* __restrict__ bk,
    const float* __restrict__ bv)
{
    extern __shared__ char smem[];
    const uint32_t sb = smem_to_u32(smem);
    const int tid = threadIdx.x;
    const int lane = tid & 31;
    const int w = tid >> 5;
    const int m0 = blockIdx.x * 128;

    const uint32_t sXH = sb + PXH_OFF, sXL = sb + PXL_OFF;
    uint32_t sWH[2] = {sb + PW_OFF, sb + PW_OFF + 2 * PWBUF};
    uint32_t sWL[2] = {sb + PW_OFF + PWBUF, sb + PW_OFF + 3 * PWBUF};

    // ---- prefetch W chunk 0 (wsel=0, k0=0) ----
#pragma unroll
    for (int i = 0; i < 4; i++) {
        int idx = tid + i * 256;            // 1024 16B-lines per half
        int row = idx >> 5, c16 = idx & 31;
        uint32_t d = (uint32_t)row * RSB + c16 * 16;
        size_t g = (size_t)row * DIM + c16 * 8;
        cp16(sWH[0] + d, g_Wh + g);
        cp16(sWL[0] + d, g_Wl + g);
    }
    CP_COMMIT();

    // ---- load + split resident x tile ----
    {
#pragma unroll
        for (int i = 0; i < 32; i++) {
            int idx = tid + i * 256;        // 8192 float4
            int row = idx >> 6, c4 = idx & 63;
            float4 v = *(const float4*)&x[(size_t)(m0 + row) * DIM + c4 * 4];
            __nv_bfloat16 h[4], l[4];
            split2(v.x, h[0], l[0]); split2(v.y, h[1], l[1]);
            split2(v.z, h[2], l[2]); split2(v.w, h[3], l[3]);
            uint32_t d = (uint32_t)row * RSB + c4 * 8;
            *(uint2*)(smem + PXH_OFF + d) = make_uint2(pack_bf(h[0], h[1]), pack_bf(h[2], h[3]));
            *(uint2*)(smem + PXL_OFF + d) = make_uint2(pack_bf(l[0], l[1]), pack_bf(l[2], l[3]));
        }
    }

    // ldmatrix addressing
    const uint32_t aoff = (uint32_t)(16 * w + (lane & 15)) * RSB + ((lane & 16) ? 16u : 0u);
    const uint32_t boff = (uint32_t)((lane & 7) + ((lane & 8) ? 8 : 0)) * RSB + ((lane & 16) ? 16u : 0u);

    float oacc[32][4];
#pragma unroll
    for (int i = 0; i < 32; i++)
#pragma unroll
        for (int j = 0; j < 4; j++) oacc[i][j] = 0.f;

#pragma unroll 1
    for (int c = 0; c < 24; c++) {
        const int buf = c & 1;
        // prefetch chunk c+1
        if (c < 23) {
            const int wsel = (c + 1) >> 3;
            const int k0 = ((c + 1) & 7) * 32;
            const size_t gbase = (size_t)wsel * DIM * DIM + (size_t)k0 * DIM;
#pragma unroll
            for (int i = 0; i < 4; i++) {
                int idx = tid + i * 256;
                int row = idx >> 5, c16 = idx & 31;
                uint32_t d = (uint32_t)row * RSB + c16 * 16;
                size_t g = gbase + (size_t)row * DIM + c16 * 8;
                cp16(sWH[buf ^ 1] + d, g_Wh + g);
                cp16(sWL[buf ^ 1] + d, g_Wl + g);
            }
            CP_COMMIT();
            CP_WAIT(1);
        } else {
            CP_WAIT(0);
        }
        __syncthreads();

        // compute chunk c: 2 ksteps of 16
        const int kbase = (c & 7) * 32;
#pragma unroll
        for (int ks = 0; ks < 2; ks++) {
            uint32_t ah[4], al[4];
            ldsm_x4(ah, sXH + aoff + (uint32_t)(kbase + ks * 16) * 2);
            ldsm_x4(al, sXL + aoff + (uint32_t)(kbase + ks * 16) * 2);
#pragma unroll
            for (int nt = 0; nt < 16; nt++) {
                uint32_t bh[4], bl[4];
                uint32_t a = (uint32_t)ks * 16 * RSB + boff + (uint32_t)nt * 32;
                ldsm_x4_t(bh, sWH[buf] + a);
                ldsm_x4_t(bl, sWL[buf] + a);
#pragma unroll
                for (int h = 0; h < 2; h++) {
                    const int nto = nt * 2 + h;
                    mma_bf16(oacc[nto], ah, &bh[2 * h]);
                    mma_bf16(oacc[nto], ah, &bl[2 * h]);
                    mma_bf16(oacc[nto], al, &bh[2 * h]);
                }
            }
        }

        // ---- end of a weight: epilogue ----
        if ((c & 7) == 7) {
            const int wsel = c >> 3;
            const float* bias = (wsel == 0) ? bq : (wsel == 1) ? bk : bv;
            __nv_bfloat16* oh = (wsel == 0) ? g_Qh : (wsel == 1) ? g_Kh : g_Vh;
            __nv_bfloat16* ol = (wsel == 0) ? g_Ql : (wsel == 1) ? g_Kl : g_Vl;

            const int r0 = m0 + 16 * w + (lane >> 2);
            const size_t base0 = (size_t)r0 * DIM + (lane & 3) * 2;
            const size_t base1 = base0 + (size_t)8 * DIM;
#pragma unroll
            for (int nto = 0; nto < 32; nto++) {
                const int col = nto * 8 + (lane & 3) * 2;
                float b0 = bias[col], b1 = bias[col + 1];
                __nv_bfloat16 h0, l0, h1, l1;
                split2(oacc[nto][0] + b0, h0, l0);
                split2(oacc[nto][1] + b1, h1, l1);
                *(uint32_t*)&oh[base0 + nto * 8] = pack_bf(h0, h1);
                *(uint32_t*)&ol[base0 + nto * 8] = pack_bf(l0, l1);
                split2(oacc[nto][2] + b0, h0, l0);
                split2(oacc[nto][3] + b1, h1, l1);
                *(uint32_t*)&oh[base1 + nto * 8] = pack_bf(h0, h1);
                *(uint32_t*)&ol[base1 + nto * 8] = pack_bf(l0, l1);
                oacc[nto][0] = oacc[nto][1] = oacc[nto][2] = oacc[nto][3] = 0.f;
            }
        }
        __syncthreads();
    }
}

// ---------------------------------------------------------------------------
// Attention via mma.sync bf16 (3-pass split). CTA = 128 queries x batch.
// (unchanged from R3 — proven at 620us, rel_err 1.4e-5)
// ---------------------------------------------------------------------------
#define QH_OFF 0
#define QL_OFF (128 * RSB)
#define KH_OFF (QL_OFF + 128 * RSB)
#define KL_OFF (KH_OFF + 32 * RSB)
#define VH_OFF (KL_OFF + 32 * RSB)
#define VL_OFF (VH_OFF + 32 * RSB)
#define ATTN_SMEM (VL_OFF + 32 * RSB)

__global__ __launch_bounds__(256, 1) void attn_mma(float* __restrict__ out)
{
    extern __shared__ char smem[];
    const uint32_t sb = smem_to_u32(smem);
    const int tid = threadIdx.x;
    const int lane = tid & 31;
    const int w = tid >> 5;
    const int b = blockIdx.y;
    const int q0 = blockIdx.x * 128;

    const uint32_t sQH = sb + QH_OFF, sQL = sb + QL_OFF;
    const uint32_t sKH = sb + KH_OFF, sKL = sb + KL_OFF;
    const uint32_t sVH = sb + VH_OFF, sVL = sb + VL_OFF;

    {
        const size_t qg = (size_t)(b * SEQ + q0) * DIM;
#pragma unroll
        for (int i = 0; i < 16; i++) {
            int idx = tid + i * 256;
            int row = idx >> 5, ch = idx & 31;
            uint32_t d = (uint32_t)row * RSB + ch * 16;
            size_t g = qg + (size_t)row * DIM + ch * 8;
            cp16(sQH + d, g_Qh + g);
            cp16(sQL + d, g_Ql + g);
        }
        const size_t kg = (size_t)b * SEQ * DIM;
#pragma unroll
        for (int i = 0; i < 4; i++) {
            int idx = tid + i * 256;
            int row = idx >> 5, ch = idx & 31;
            uint32_t d = (uint32_t)row * RSB + ch * 16;
            size_t g = kg + (size_t)row * DIM + ch * 8;
            cp16(sKH + d, g_Kh + g);
            cp16(sKL + d, g_Kl + g);
            cp16(sVH + d, g_Vh + g);
            cp16(sVL + d, g_Vl + g);
        }
    }
    CP_COMMIT();
    CP_WAIT(0);
    __syncthreads();

    const uint32_t qoff = (uint32_t)(16 * w + (lane & 15)) * RSB + ((lane & 16) ? 16u : 0u);
    const uint32_t koff = (uint32_t)((lane & 7) + ((lane & 16) ? 8 : 0)) * RSB + ((lane & 8) ? 16u : 0u);
    const uint32_t voff = (uint32_t)((lane & 7) + ((lane & 8) ? 8 : 0)) * RSB + ((lane & 16) ? 16u : 0u);

    float oacc[32][4];
#pragma unroll
    for (int i = 0; i < 32; i++)
#pragma unroll
        for (int j = 0; j < 4; j++) oacc[i][j] = 0.f;
    float lsum0 = 0.f, lsum1 = 0.f;

    const float SC = 0.0625f * 1.4426950408889634f;

#pragma unroll 1
    for (int kt = 0; kt < 128; kt++) {
        float sacc[4][4];
#pragma unroll
        for (int i = 0; i < 4; i++)
#pragma unroll
            for (int j = 0; j < 4; j++) sacc[i][j] = 0.f;

#pragma unroll 4
        for (int ks = 0; ks < 16; ks++) {
            uint32_t qh[4], ql[4], kf[2][4], lf[2][4];
            ldsm_x4(qh, sQH + qoff + ks * 32);
            ldsm_x4(ql, sQL + qoff + ks * 32);
#pragma unroll
            for (int np = 0; np < 2; np++) {
                ldsm_x4(kf[np], sKH + koff + (uint32_t)np * 16 * RSB + ks * 32);
                ldsm_x4(lf[np], sKL + koff + (uint32_t)np * 16 * RSB + ks * 32);
            }
#pragma unroll
            for (int np = 0; np < 2; np++)
#pragma unroll
                for (int h = 0; h < 2; h++) {
                    const int nt = np * 2 + h;
                    mma_bf16(sacc[nt], qh, &kf[np][2 * h]);
                    mma_bf16(sacc[nt], qh, &lf[np][2 * h]);
                    mma_bf16(sacc[nt], ql, &kf[np][2 * h]);
                }
        }
        __syncthreads();

        if (kt < 127) {
            const size_t kg = ((size_t)b * SEQ + (size_t)(kt + 1) * 32) * DIM;
#pragma unroll
            for (int i = 0; i < 4; i++) {
                int idx = tid + i * 256;
                int row = idx >> 5, ch = idx & 31;
                uint32_t d = (uint32_t)row * RSB + ch * 16;
                size_t g = kg + (size_t)row * DIM + ch * 8;
                cp16(sKH + d, g_Kh + g);
                cp16(sKL + d, g_Kl + g);
            }
            CP_COMMIT();
        }

        uint32_t Ph[2][4], Pl[2][4];
#pragma unroll
        for (int nt = 0; nt < 4; nt++) {
            float p0 = exp2f(sacc[nt][0] * SC);
            float p1 = exp2f(sacc[nt][1] * SC);
            float p2 = exp2f(sacc[nt][2] * SC);
            float p3 = exp2f(sacc[nt][3] * SC);
            lsum0 += p0 + p1;
            lsum1 += p2 + p3;
            __nv_bfloat16 h0, l0, h1, l1, h2, l2, h3, l3;
            split2(p0, h0, l0); split2(p1, h1, l1);
            split2(p2, h2, l2); split2(p3, h3, l3);
            const int j = nt >> 1, bs = (nt & 1) * 2;
            Ph[j][bs]     = pack_bf(h0, h1);
            Ph[j][bs + 1] = pack_bf(h2, h3);
            Pl[j][bs]     = pack_bf(l0, l1);
            Pl[j][bs + 1] = pack_bf(l2, l3);
        }

        if (kt < 127) { CP_WAIT(1); } else { CP_WAIT(0); }
        __syncthreads();

#pragma unroll
        for (int dblk = 0; dblk < 4; dblk++)
#pragma unroll
            for (int kc = 0; kc < 2; kc++) {
                uint32_t vhf[4][4], vlf[4][4];
#pragma unroll
                for (int q = 0; q < 4; q++) {
                    uint32_t a = (uint32_t)kc * 16 * RSB + voff + (uint32_t)(dblk * 64 + q * 16) * 2;
                    ldsm_x4_t(vhf[q], sVH + a);
                    ldsm_x4_t(vlf[q], sVL + a);
                }
#pragma unroll
                for (int q = 0; q < 4; q++)
#pragma unroll
                    for (int h = 0; h < 2; h++) {
                        const int nto = dblk * 8 + q * 2 + h;
                        mma_bf16(oacc[nto], Ph[kc], &vhf[q][2 * h]);
                        mma_bf16(oacc[nto], Ph[kc], &vlf[q][2 * h]);
                        mma_bf16(oacc[nto], Pl[kc], &vhf[q][2 * h]);
                    }
            }
        __syncthreads();

        if (kt < 127) {
            const size_t vg = ((size_t)b * SEQ + (size_t)(kt + 1) * 32) * DIM;
#pragma unroll
            for (int i = 0; i < 4; i++) {
                int idx = tid + i * 256;
                int row = idx >> 5, ch = idx & 31;
                uint32_t d = (uint32_t)row * RSB + ch * 16;
                size_t g = vg + (size_t)row * DIM + ch * 8;
                cp16(sVH + d, g_Vh + g);
                cp16(sVL + d, g_Vl + g);
            }
            CP_COMMIT();
            CP_WAIT(1);
        }
        __syncthreads();
    }

    lsum0 += __shfl_xor_sync(0xffffffffu, lsum0, 1);
    lsum0 += __shfl_xor_sync(0xffffffffu, lsum0, 2);
    lsum1 += __shfl_xor_sync(0xffffffffu, lsum1, 1);
    lsum1 += __shfl_xor_sync(0xffffffffu, lsum1, 2);
    const float inv0 = 1.0f / lsum0;
    const float inv1 = 1.0f / lsum1;

    const int r0 = q0 + 16 * w + (lane >> 2);
    const size_t base0 = ((size_t)b * SEQ + r0) * DIM + (lane & 3) * 2;
    const size_t base1 = base0 + (size_t)8 * DIM;
#pragma unroll
    for (int nto = 0; nto < 32; nto++) {
        float2 v0 = make_float2(oacc[nto][0] * inv0, oacc[nto][1] * inv0);
        float2 v1 = make_float2(oacc[nto][2] * inv1, oacc[nto][3] * inv1);
        *(float2*)&out[base0 + nto * 8] = v0;
        *(float2*)&out[base1 + nto * 8] = v1;
    }
}

// ---------------------------------------------------------------------------
extern "C" void kernel_launch(void* const* d_in, const int* in_sizes, int n_in,
                              void* d_out, int out_size)
{
    const float* x  = (const float*)d_in[0];
    const float* Wk = (const float*)d_in[1];
    const float* bk = (const float*)d_in[2];
    const float* Wq = (const float*)d_in[3];
    const float* bq = (const float*)d_in[4];
    const float* Wv = (const float*)d_in[5];
    const float* bv = (const float*)d_in[6];
    float* out = (float*)d_out;

    split_w_kernel<<<dim3(64, 3), 256>>>(Wq, Wk, Wv);

    cudaFuncSetAttribute(proj_mma, cudaFuncAttributeMaxDynamicSharedMemorySize,
                         PROJ_SMEM);
    proj_mma<<<BATCH * SEQ / 128, 256, PROJ_SMEM>>>(x, bq, bk, bv);

    cudaFuncSetAttribute(attn_mma, cudaFuncAttributeMaxDynamicSharedMemorySize,
                         ATTN_SMEM);
    attn_mma<<<dim3(SEQ / 128, BATCH), 256, ATTN_SMEM>>>(out);
}